// round 10
// baseline (speedup 1.0000x reference)
#include <cuda_runtime.h>
#include <cuda_fp16.h>
#include <cstdint>

#define EPS 1e-5f

__device__ __forceinline__ float tanh_fast(float x) {
    float y; asm("tanh.approx.f32 %0,%1;" : "=f"(y) : "f"(x)); return y;
}
__device__ __forceinline__ unsigned tanh2(unsigned v) {
    unsigned y; asm("tanh.approx.f16x2 %0,%1;" : "=r"(y) : "r"(v)); return y;
}
__device__ __forceinline__ unsigned packh2(float a, float b) {
    __half2 h = __floats2half2_rn(a, b);
    return *reinterpret_cast<unsigned*>(&h);
}

__device__ __forceinline__ void mma16(float* d,
                                      unsigned a0, unsigned a1, unsigned a2, unsigned a3,
                                      unsigned b0, unsigned b1) {
    asm volatile(
        "mma.sync.aligned.m16n8k16.row.col.f32.f16.f16.f32 "
        "{%0,%1,%2,%3},{%4,%5,%6,%7},{%8,%9},{%0,%1,%2,%3};"
        : "+f"(d[0]), "+f"(d[1]), "+f"(d[2]), "+f"(d[3])
        : "r"(a0), "r"(a1), "r"(a2), "r"(a3), "r"(b0), "r"(b1));
}

__device__ __forceinline__ void ldsm4(unsigned& r0, unsigned& r1, unsigned& r2, unsigned& r3,
                                      unsigned addr) {
    asm volatile("ldmatrix.sync.aligned.m8n8.x4.shared.b16 {%0,%1,%2,%3},[%4];"
                 : "=r"(r0), "=r"(r1), "=r"(r2), "=r"(r3) : "r"(addr));
}

// hb row stride: 72 halfs = 36 u32 words -> 4r mod 32 distinct => conflict-free
#define HSTRW 36

__device__ __forceinline__ void init_bias(float d[2][8][4], const float* __restrict__ sb, int tg) {
#pragma unroll
    for (int nt = 0; nt < 8; nt++) {
        float2 bb = *(const float2*)&sb[8 * nt + 2 * tg];
        d[0][nt][0] = bb.x; d[0][nt][1] = bb.y; d[0][nt][2] = bb.x; d[0][nt][3] = bb.y;
        d[1][nt][0] = bb.x; d[1][nt][1] = bb.y; d[1][nt][2] = bb.x; d[1][nt][3] = bb.y;
    }
}

template <int NKK>
__device__ __forceinline__ void mma_layer(float d[2][8][4], const uint4* __restrict__ bf,
                                          const unsigned a_base0, const unsigned a_base1,
                                          int lane) {
#pragma unroll
    for (int kk = 0; kk < NKK; kk++) {
        unsigned A[2][4];
        ldsm4(A[0][0], A[0][1], A[0][2], A[0][3], a_base0 + kk * 32);
        ldsm4(A[1][0], A[1][1], A[1][2], A[1][3], a_base1 + kk * 32);
#pragma unroll
        for (int ntp = 0; ntp < 4; ntp++) {
            uint4 b = bf[(kk * 4 + ntp) * 32 + lane];
            mma16(d[0][2 * ntp],     A[0][0], A[0][1], A[0][2], A[0][3], b.x, b.y);
            mma16(d[1][2 * ntp],     A[1][0], A[1][1], A[1][2], A[1][3], b.x, b.y);
            mma16(d[0][2 * ntp + 1], A[0][0], A[0][1], A[0][2], A[0][3], b.z, b.w);
            mma16(d[1][2 * ntp + 1], A[1][0], A[1][1], A[1][2], A[1][3], b.z, b.w);
        }
    }
}

// One-pass LN; STORE=true: pack -> tanh.f16x2 -> store half2. STORE=false: f32 tanh in regs.
template <bool STORE>
__device__ __forceinline__ void ln_tanh_frag(float d[2][8][4],
                                             const float* __restrict__ sg,
                                             const float* __restrict__ sbe,
                                             unsigned* __restrict__ hbu, int g, int tg) {
#pragma unroll
    for (int mt = 0; mt < 2; mt++) {
        float s1 = 0.f, q1 = 0.f, s2 = 0.f, q2 = 0.f;
#pragma unroll
        for (int nt = 0; nt < 8; nt++) {
            float a = d[mt][nt][0], b = d[mt][nt][1];
            float c = d[mt][nt][2], e = d[mt][nt][3];
            s1 += a + b; q1 = fmaf(a, a, q1); q1 = fmaf(b, b, q1);
            s2 += c + e; q2 = fmaf(c, c, q2); q2 = fmaf(e, e, q2);
        }
        s1 += __shfl_xor_sync(0xffffffffu, s1, 1); q1 += __shfl_xor_sync(0xffffffffu, q1, 1);
        s2 += __shfl_xor_sync(0xffffffffu, s2, 1); q2 += __shfl_xor_sync(0xffffffffu, q2, 1);
        s1 += __shfl_xor_sync(0xffffffffu, s1, 2); q1 += __shfl_xor_sync(0xffffffffu, q1, 2);
        s2 += __shfl_xor_sync(0xffffffffu, s2, 2); q2 += __shfl_xor_sync(0xffffffffu, q2, 2);
        float m1 = s1 * (1.f / 64.f), m2 = s2 * (1.f / 64.f);
        float i1 = rsqrtf(fmaf(-m1, m1, q1 * (1.f / 64.f)) + EPS);
        float i2 = rsqrtf(fmaf(-m2, m2, q2 * (1.f / 64.f)) + EPS);
#pragma unroll
        for (int nt = 0; nt < 8; nt++) {
            float2 gg = *(const float2*)&sg[8 * nt + 2 * tg];
            float2 bb = *(const float2*)&sbe[8 * nt + 2 * tg];
            float y0 = fmaf((d[mt][nt][0] - m1) * i1, gg.x, bb.x);
            float y1 = fmaf((d[mt][nt][1] - m1) * i1, gg.y, bb.y);
            float y2 = fmaf((d[mt][nt][2] - m2) * i2, gg.x, bb.x);
            float y3 = fmaf((d[mt][nt][3] - m2) * i2, gg.y, bb.y);
            if (STORE) {
                hbu[(16 * mt + g) * HSTRW + 4 * nt + tg]     = tanh2(packh2(y0, y1));
                hbu[(16 * mt + g + 8) * HSTRW + 4 * nt + tg] = tanh2(packh2(y2, y3));
            } else {
                d[mt][nt][0] = tanh_fast(y0);
                d[mt][nt][1] = tanh_fast(y1);
                d[mt][nt][2] = tanh_fast(y2);
                d[mt][nt][3] = tanh_fast(y3);
            }
        }
    }
}

// smem layout (float units):
// BF0 [512] @0 | BF1 [2048] @512 | BF2 [2048] @2560
// params @4608: sb0,sb1,sb2,sg0,sbe0,sg1,sbe1,sg2,sbe2,sw3 (64 each) -> 5248
// hb @5248: 8 warps x 32 rows x 72 halfs (=1152 floats/warp)
#define SMEM_FLOATS (5248 + 8 * 1152)

__global__ __launch_bounds__(256, 2) void edge_mlp_tc(
    const float* __restrict__ x, const int* __restrict__ ei,
    const float* __restrict__ W0, const float* __restrict__ b0,
    const float* __restrict__ g0, const float* __restrict__ be0,
    const float* __restrict__ W1, const float* __restrict__ b1,
    const float* __restrict__ g1, const float* __restrict__ be1,
    const float* __restrict__ W2, const float* __restrict__ b2,
    const float* __restrict__ g2, const float* __restrict__ be2,
    const float* __restrict__ W3, const float* __restrict__ b3,
    float* __restrict__ out, int n_edges)
{
    extern __shared__ float sm[];
    uint4* BF0 = (uint4*)(sm);
    uint4* BF1 = (uint4*)(sm + 512);
    uint4* BF2 = (uint4*)(sm + 2560);
    float* sb0 = sm + 4608; float* sb1 = sm + 4672; float* sb2 = sm + 4736;
    float* sg0 = sm + 4800; float* sbe0 = sm + 4864;
    float* sg1 = sm + 4928; float* sbe1 = sm + 4992;
    float* sg2 = sm + 5056; float* sbe2 = sm + 5120;
    float* sw3 = sm + 5184;

    const int tid = threadIdx.x;

    // Stage B fragments as uint4 = {uint2 frag of nt=2ntp, uint2 frag of nt=2ntp+1}
    // frag(nt): b0 = {W[k0][n],W[k0+1][n]}, b1 = {W[k0+8][n],W[k0+9][n]}, n=8nt+g, k0=16kk+2t
    {
        int i = tid;
        if (i < 128) {   // BF0: kk=0 only, ntp=0..3
            int ntp = i >> 5, ln = i & 31, gg = ln >> 2, tt = ln & 3;
            int k0 = 2 * tt;
            int n0 = 8 * (2 * ntp) + gg, n1 = 8 * (2 * ntp + 1) + gg;
            BF0[i] = make_uint4(
                packh2(W0[k0 * 64 + n0],       W0[(k0 + 1) * 64 + n0]),
                packh2(W0[(k0 + 8) * 64 + n0], W0[(k0 + 9) * 64 + n0]),
                packh2(W0[k0 * 64 + n1],       W0[(k0 + 1) * 64 + n1]),
                packh2(W0[(k0 + 8) * 64 + n1], W0[(k0 + 9) * 64 + n1]));
        }
    }
    for (int i = tid; i < 512; i += 256) {   // BF1/BF2: kk=0..3, ntp=0..3
        int kk = i >> 7, ntp = (i >> 5) & 3, ln = i & 31, gg = ln >> 2, tt = ln & 3;
        int k0 = 16 * kk + 2 * tt;
        int n0 = 8 * (2 * ntp) + gg, n1 = 8 * (2 * ntp + 1) + gg;
        BF1[i] = make_uint4(
            packh2(W1[k0 * 64 + n0],       W1[(k0 + 1) * 64 + n0]),
            packh2(W1[(k0 + 8) * 64 + n0], W1[(k0 + 9) * 64 + n0]),
            packh2(W1[k0 * 64 + n1],       W1[(k0 + 1) * 64 + n1]),
            packh2(W1[(k0 + 8) * 64 + n1], W1[(k0 + 9) * 64 + n1]));
        BF2[i] = make_uint4(
            packh2(W2[k0 * 64 + n0],       W2[(k0 + 1) * 64 + n0]),
            packh2(W2[(k0 + 8) * 64 + n0], W2[(k0 + 9) * 64 + n0]),
            packh2(W2[k0 * 64 + n1],       W2[(k0 + 1) * 64 + n1]),
            packh2(W2[(k0 + 8) * 64 + n1], W2[(k0 + 9) * 64 + n1]));
    }
    if (tid < 64) {
        sb0[tid] = b0[tid]; sb1[tid] = b1[tid]; sb2[tid] = b2[tid];
        sg0[tid] = g0[tid]; sbe0[tid] = be0[tid];
        sg1[tid] = g1[tid]; sbe1[tid] = be1[tid];
        sg2[tid] = g2[tid]; sbe2[tid] = be2[tid];
        sw3[tid] = W3[tid];
    }
    __syncthreads();
    const float b3v = b3[0];

    const int lane = tid & 31, wid = tid >> 5;
    const int g = lane >> 2, tg = lane & 3;
    unsigned* hbu = (unsigned*)(sm + 5248) + wid * (32 * HSTRW);
    const float4* x4 = (const float4*)x;

    // ldmatrix lane addresses: mat0 rows0-7/cols0-7, mat1 rows8-15/cols0-7,
    // mat2 rows0-7/cols8-15, mat3 rows8-15/cols8-15 (matches a0..a3)
    const int lrow = (lane & 7) | ((lane & 8));       // 0-7, 8-15, 0-7, 8-15 (+8 via bit3)
    const int lc4 = ((lane >> 4) & 1) * 4;            // word offset for cols 8-15
    unsigned a_base0 = (unsigned)__cvta_generic_to_shared(&hbu[lrow * HSTRW + lc4]);
    unsigned a_base1 = (unsigned)__cvta_generic_to_shared(&hbu[(16 + lrow) * HSTRW + lc4]);

    const int tile_stride = gridDim.x * 8 * 32;
    for (int base = (blockIdx.x * 8 + wid) * 32; base < n_edges; base += tile_stride) {
        // gather 32 edges -> hb row `lane`, 16 halfs
        int e = base + lane; if (e >= n_edges) e = n_edges - 1;
        int si = ei[e], di = ei[n_edges + e];
        float4 A0 = x4[2 * si], A1 = x4[2 * si + 1];
        float4 C0 = x4[2 * di], C1 = x4[2 * di + 1];
        {
            unsigned* hr = &hbu[lane * HSTRW];
            *(uint4*)&hr[0] = make_uint4(packh2(A0.x, A0.y), packh2(A0.z, A0.w),
                                         packh2(A1.x, A1.y), packh2(A1.z, A1.w));
            *(uint4*)&hr[4] = make_uint4(packh2(C0.x, C0.y), packh2(C0.z, C0.w),
                                         packh2(C1.x, C1.y), packh2(C1.z, C1.w));
        }
        __syncwarp();

        float d[2][8][4];

        // layer 0: K=16
        init_bias(d, sb0, tg);
        mma_layer<1>(d, BF0, a_base0, a_base1, lane);
        __syncwarp();
        ln_tanh_frag<true>(d, sg0, sbe0, hbu, g, tg);
        __syncwarp();

        // layer 1: K=64
        init_bias(d, sb1, tg);
        mma_layer<4>(d, BF1, a_base0, a_base1, lane);
        __syncwarp();
        ln_tanh_frag<true>(d, sg1, sbe1, hbu, g, tg);
        __syncwarp();

        // layer 2: K=64 (output stays in registers, f32 tanh)
        init_bias(d, sb2, tg);
        mma_layer<4>(d, BF2, a_base0, a_base1, lane);
        __syncwarp();   // hb reads done -> safe to overwrite next iteration
        ln_tanh_frag<false>(d, sg2, sbe2, hbu, g, tg);

        // layer 3: 64 -> 1, butterfly reduce over the 4-lane group
#pragma unroll
        for (int mt = 0; mt < 2; mt++) {
            float p1 = 0.f, p2 = 0.f;
#pragma unroll
            for (int nt = 0; nt < 8; nt++) {
                float2 w = *(const float2*)&sw3[8 * nt + 2 * tg];
                p1 = fmaf(d[mt][nt][0], w.x, p1); p1 = fmaf(d[mt][nt][1], w.y, p1);
                p2 = fmaf(d[mt][nt][2], w.x, p2); p2 = fmaf(d[mt][nt][3], w.y, p2);
            }
            p1 += __shfl_xor_sync(0xffffffffu, p1, 1); p1 += __shfl_xor_sync(0xffffffffu, p1, 2);
            p2 += __shfl_xor_sync(0xffffffffu, p2, 1); p2 += __shfl_xor_sync(0xffffffffu, p2, 2);
            if (tg == 0) {
                int e1 = base + 16 * mt + g, e2 = e1 + 8;
                if (e1 < n_edges) out[e1] = p1 + b3v;
                if (e2 < n_edges) out[e2] = p2 + b3v;
            }
        }
        __syncwarp();
    }
}

extern "C" void kernel_launch(void* const* d_in, const int* in_sizes, int n_in,
                              void* d_out, int out_size) {
    const float* x   = (const float*)d_in[0];
    const int*   ei  = (const int*)d_in[1];
    const float* W0 = (const float*)d_in[2];
    const float* b0 = (const float*)d_in[3];
    const float* g0 = (const float*)d_in[4];
    const float* be0 = (const float*)d_in[5];
    const float* W1 = (const float*)d_in[6];
    const float* b1 = (const float*)d_in[7];
    const float* g1 = (const float*)d_in[8];
    const float* be1 = (const float*)d_in[9];
    const float* W2 = (const float*)d_in[10];
    const float* b2 = (const float*)d_in[11];
    const float* g2 = (const float*)d_in[12];
    const float* be2 = (const float*)d_in[13];
    const float* W3 = (const float*)d_in[14];
    const float* b3 = (const float*)d_in[15];
    float* out = (float*)d_out;

    const int n_edges = in_sizes[1] / 2;
    const size_t smem_bytes = SMEM_FLOATS * sizeof(float);  // ~57 KB

    static bool attr_set = false;
    if (!attr_set) {
        cudaFuncSetAttribute(edge_mlp_tc, cudaFuncAttributeMaxDynamicSharedMemorySize,
                             (int)smem_bytes);
        attr_set = true;
    }

    const int threads = 256;
    const int blocks = 296;  // 2 resident blocks/SM, grid-stride
    edge_mlp_tc<<<blocks, threads, smem_bytes>>>(x, ei,
                                                 W0, b0, g0, be0,
                                                 W1, b1, g1, be1,
                                                 W2, b2, g2, be2,
                                                 W3, b3, out, n_edges);
}